// round 1
// baseline (speedup 1.0000x reference)
#include <cuda_runtime.h>
#include <math.h>

#define BB 32768
#define DD 64
#define HH 256

// ---------------- device scratch (static, no runtime allocation) ----------------
__device__ float g_y[BB*DD];
__device__ float g_logp[BB];
__device__ float g_kz[6][BB*DD];
__device__ float g_kd[6][BB];
__device__ float g_c[BB*HH];
__device__ float g_csum[BB];

// ---------------- init: copy y, zero logp ----------------
__global__ void init_kernel(const float* __restrict__ y){
    int i = blockIdx.x*256 + threadIdx.x;      // grid covers BB*DD exactly
    g_y[i] = y[i];
    if (i < BB) g_logp[i] = 0.f;
}

// ---------------- precompute: c = (e@W2^T) * (e@W1z), csum = row-sum(c) ----------------
__global__ __launch_bounds__(512,1) void precompute_kernel(
    const float* __restrict__ e, const float* __restrict__ W1, const float* __restrict__ W2){
    extern __shared__ float sm[];
    float* W1s = sm;            // [64][256]
    float* W2T = sm + 16384;    // [64][256]  (transposed W2)
    float* es  = sm + 32768;    // [64][64]
    int tid = threadIdx.x;
    int row0 = blockIdx.x*64;

    for (int i=tid; i<4096; i+=512) ((float4*)W1s)[i] = ((const float4*)W1)[i];
    for (int i=tid; i<HH*DD; i+=512){ int h = i>>6, d = i&63; W2T[d*HH + h] = W2[i]; }
    for (int i=tid; i<1024; i+=512) ((float4*)es)[i] = ((const float4*)(e + (size_t)row0*DD))[i];
    __syncthreads();

    int ry = tid>>5, hx = tid&31;   // rows ry*4..+3, h cols hx*8..+7
    float s1[4][8], s2[4][8];
    #pragma unroll
    for (int i=0;i<4;i++)
        #pragma unroll
        for (int j=0;j<8;j++){ s1[i][j]=0.f; s2[i][j]=0.f; }

    for (int d=0; d<DD; d++){
        float ev[4];
        #pragma unroll
        for (int i=0;i<4;i++) ev[i] = es[(ry*4+i)*DD + d];
        const float* p1 = &W1s[d*HH + hx*8];
        const float* p2 = &W2T[d*HH + hx*8];
        float4 a1 = *(const float4*)p1,  b1v = *(const float4*)(p1+4);
        float4 a2 = *(const float4*)p2,  b2v = *(const float4*)(p2+4);
        float w1v[8] = {a1.x,a1.y,a1.z,a1.w,b1v.x,b1v.y,b1v.z,b1v.w};
        float w2v[8] = {a2.x,a2.y,a2.z,a2.w,b2v.x,b2v.y,b2v.z,b2v.w};
        #pragma unroll
        for (int i=0;i<4;i++)
            #pragma unroll
            for (int j=0;j<8;j++){
                s2[i][j] = fmaf(ev[i], w1v[j], s2[i][j]);
                s1[i][j] = fmaf(ev[i], w2v[j], s1[i][j]);
            }
    }
    #pragma unroll
    for (int i=0;i<4;i++){
        float cv[8]; float p = 0.f;
        #pragma unroll
        for (int j=0;j<8;j++){ cv[j] = s1[i][j]*s2[i][j]; p += cv[j]; }
        int r = row0 + ry*4 + i;
        float4* dst = (float4*)&g_c[(size_t)r*HH + hx*8];
        dst[0] = make_float4(cv[0],cv[1],cv[2],cv[3]);
        dst[1] = make_float4(cv[4],cv[5],cv[6],cv[7]);
        #pragma unroll
        for (int o=16;o;o>>=1) p += __shfl_xor_sync(0xffffffffu, p, o);
        if (hx==0) g_csum[r] = p;
    }
}

// ---------------- fused RHS: yi = y + sum cf_j*k_j ; k_stage = (h@W2+b2, sum c*h^2 - csum) ----------------
#define SMEM_RHS_BYTES (49600*4)

__global__ __launch_bounds__(512,1) void rhs_kernel(
    float t, int stage, float c0,float c1,float c2,float c3,float c4,
    const float* __restrict__ W1, const float* __restrict__ b1,
    const float* __restrict__ W2, const float* __restrict__ b2){
    extern __shared__ float sm[];
    float* W1s = sm;              // [64][256]   16384
    float* W2s = sm + 16384;      // [256][64]   16384
    float* zs  = sm + 32768;      // [128][64]    8192
    float* hs  = sm + 40960;      // [128][65]    8320 (padded vs bank conflicts)
    float* tb  = sm + 49280;      // [256]
    float* b2s = sm + 49536;      // [64]
    int tid = threadIdx.x;
    int row0 = blockIdx.x*128;

    for (int i=tid; i<4096; i+=512) ((float4*)W1s)[i] = ((const float4*)W1)[i];
    for (int i=tid; i<4096; i+=512) ((float4*)W2s)[i] = ((const float4*)W2)[i];
    if (tid < HH)               tb[tid]      = fmaf(t, W1[DD*HH + tid], b1[tid]);
    if (tid >= HH && tid < HH+DD) b2s[tid-HH] = b2[tid-HH];

    const float cf[5] = {c0,c1,c2,c3,c4};
    {
        const float4* ybase = (const float4*)(g_y + (size_t)row0*DD);
        for (int i=tid; i<2048; i+=512){
            float4 v = ybase[i];
            for (int j=0;j<stage;j++){
                float4 k = ((const float4*)(g_kz[j] + (size_t)row0*DD))[i];
                v.x = fmaf(cf[j],k.x,v.x); v.y = fmaf(cf[j],k.y,v.y);
                v.z = fmaf(cf[j],k.z,v.z); v.w = fmaf(cf[j],k.w,v.w);
            }
            ((float4*)zs)[i] = v;
        }
    }
    __syncthreads();

    // ---- GEMM1: a[128x256] = zs[128x64] @ W1s[64x256], 8x8 per-thread tile ----
    int ry = tid>>5, hx = tid&31;      // rows ry*8..+7 ; h cols hx*8..+7
    float acc[8][8];
    #pragma unroll
    for (int i=0;i<8;i++)
        #pragma unroll
        for (int j=0;j<8;j++) acc[i][j] = 0.f;

    for (int d0=0; d0<DD; d0+=4){
        float zq[8][4];
        #pragma unroll
        for (int i=0;i<8;i++){
            float4 z4 = *(const float4*)&zs[(ry*8+i)*DD + d0];
            zq[i][0]=z4.x; zq[i][1]=z4.y; zq[i][2]=z4.z; zq[i][3]=z4.w;
        }
        #pragma unroll
        for (int dd=0; dd<4; dd++){
            const float* wp = &W1s[(d0+dd)*HH + hx*8];
            float4 wa = *(const float4*)wp, wb = *(const float4*)(wp+4);
            float wv[8] = {wa.x,wa.y,wa.z,wa.w,wb.x,wb.y,wb.z,wb.w};
            #pragma unroll
            for (int i=0;i<8;i++){
                float zz = zq[i][dd];
                #pragma unroll
                for (int j=0;j<8;j++) acc[i][j] = fmaf(zz, wv[j], acc[i][j]);
            }
        }
    }

    // ---- bias + tanh + divergence dot (div = csum - sum c*h^2 ; store kd = -div) ----
    float tbv[8];
    #pragma unroll
    for (int j=0;j<8;j++) tbv[j] = tb[hx*8 + j];

    float divp[8];
    #pragma unroll
    for (int i=0;i<8;i++){
        #pragma unroll
        for (int j=0;j<8;j++) acc[i][j] = tanhf(acc[i][j] + tbv[j]);
        const float4* cp = (const float4*)&g_c[(size_t)(row0+ry*8+i)*HH + hx*8];
        float4 ca = cp[0], cb = cp[1];
        float p;
        p  = ca.x*acc[i][0]*acc[i][0];
        p  = fmaf(ca.y*acc[i][1], acc[i][1], p);
        p  = fmaf(ca.z*acc[i][2], acc[i][2], p);
        p  = fmaf(ca.w*acc[i][3], acc[i][3], p);
        p  = fmaf(cb.x*acc[i][4], acc[i][4], p);
        p  = fmaf(cb.y*acc[i][5], acc[i][5], p);
        p  = fmaf(cb.z*acc[i][6], acc[i][6], p);
        p  = fmaf(cb.w*acc[i][7], acc[i][7], p);
        divp[i] = p;
    }
    #pragma unroll
    for (int i=0;i<8;i++){
        float p = divp[i];
        #pragma unroll
        for (int o=16;o;o>>=1) p += __shfl_xor_sync(0xffffffffu, p, o);
        if (hx==0){ int r = row0+ry*8+i; g_kd[stage][r] = p - g_csum[r]; }
    }

    // ---- GEMM2: dz[128x64] = h[128x256] @ W2s[256x64], chunked through smem ----
    int rg = tid>>4, dg = tid&15;      // rows rg*4..+3 ; d cols dg*4..+3
    float dz[4][4];
    #pragma unroll
    for (int i=0;i<4;i++)
        #pragma unroll
        for (int j=0;j<4;j++) dz[i][j] = 0.f;

    for (int ci=0; ci<4; ci++){
        __syncthreads();
        if ((hx>>3) == ci){
            int hb = (hx&7)*8;
            #pragma unroll
            for (int i=0;i<8;i++)
                #pragma unroll
                for (int j=0;j<8;j++)
                    hs[(ry*8+i)*65 + hb + j] = acc[i][j];
        }
        __syncthreads();
        for (int hk=0; hk<64; hk++){
            float hv[4];
            #pragma unroll
            for (int i=0;i<4;i++) hv[i] = hs[(rg*4+i)*65 + hk];
            float4 w = *(const float4*)&W2s[(ci*64+hk)*DD + dg*4];
            #pragma unroll
            for (int i=0;i<4;i++){
                dz[i][0] = fmaf(hv[i], w.x, dz[i][0]);
                dz[i][1] = fmaf(hv[i], w.y, dz[i][1]);
                dz[i][2] = fmaf(hv[i], w.z, dz[i][2]);
                dz[i][3] = fmaf(hv[i], w.w, dz[i][3]);
            }
        }
    }
    float4 bb = *(const float4*)&b2s[dg*4];
    #pragma unroll
    for (int i=0;i<4;i++){
        float4 o = make_float4(dz[i][0]+bb.x, dz[i][1]+bb.y, dz[i][2]+bb.z, dz[i][3]+bb.w);
        *(float4*)&g_kz[stage][(size_t)(row0+rg*4+i)*DD + dg*4] = o;
    }
}

// ---------------- combine: y += dt*sum b_j k_j ; logp += dt*sum b_j kd_j ----------------
__global__ void combine_kernel(float dt){
    int i = blockIdx.x*256 + threadIdx.x;   // over BB*DD/4 float4
    const float b0 = (float)(35.0/384.0);
    const float b2 = (float)(500.0/1113.0);
    const float b3 = (float)(125.0/192.0);
    const float b4 = (float)(-2187.0/6784.0);
    const float b5 = (float)(11.0/84.0);
    float4 y = ((float4*)g_y)[i];
    float4 k0 = ((const float4*)g_kz[0])[i];
    float4 k2 = ((const float4*)g_kz[2])[i];
    float4 k3 = ((const float4*)g_kz[3])[i];
    float4 k4 = ((const float4*)g_kz[4])[i];
    float4 k5 = ((const float4*)g_kz[5])[i];
    float sx = b0*k0.x + b2*k2.x + b3*k3.x + b4*k4.x + b5*k5.x;
    float sy = b0*k0.y + b2*k2.y + b3*k3.y + b4*k4.y + b5*k5.y;
    float sz = b0*k0.z + b2*k2.z + b3*k3.z + b4*k4.z + b5*k5.z;
    float sw = b0*k0.w + b2*k2.w + b3*k3.w + b4*k4.w + b5*k5.w;
    y.x = fmaf(dt, sx, y.x); y.y = fmaf(dt, sy, y.y);
    y.z = fmaf(dt, sz, y.z); y.w = fmaf(dt, sw, y.w);
    ((float4*)g_y)[i] = y;
    if (i < BB){
        float s = b0*g_kd[0][i] + b2*g_kd[2][i] + b3*g_kd[3][i] + b4*g_kd[4][i] + b5*g_kd[5][i];
        g_logp[i] = fmaf(dt, s, g_logp[i]);
    }
}

// ---------------- epilogue: out = [z flat | log_px] ----------------
__global__ void final_kernel(float* __restrict__ out, int out_size){
    int gw = blockIdx.x*256 + threadIdx.x;
    int r = gw >> 5, lane = gw & 31;       // one warp per row
    float z0 = g_y[r*DD + lane];
    float z1 = g_y[r*DD + 32 + lane];
    out[r*DD + lane]      = z0;
    out[r*DD + 32 + lane] = z1;
    float s = fmaf(z0, z0, z1*z1);
    #pragma unroll
    for (int o=16;o;o>>=1) s += __shfl_xor_sync(0xffffffffu, s, o);
    if (lane==0){
        int oidx = BB*DD + r;
        if (oidx < out_size)
            out[oidx] = fmaf(-0.5f, s, -((float)DD)*0.91893853320467274178f) - g_logp[r];
    }
}

// ---------------- host ----------------
static const double A1t[1]={0.2};
static const double A2t[2]={3.0/40.0, 9.0/40.0};
static const double A3t[3]={44.0/45.0, -56.0/15.0, 32.0/9.0};
static const double A4t[4]={19372.0/6561.0, -25360.0/2187.0, 64448.0/6561.0, -212.0/729.0};
static const double A5t[5]={9017.0/3168.0, -355.0/33.0, 46732.0/5247.0, 49.0/176.0, -5103.0/18656.0};
static const double* ATAB[6]={0, A1t, A2t, A3t, A4t, A5t};
static const double CTAB[6]={0.0, 0.2, 0.3, 0.8, 8.0/9.0, 1.0};

extern "C" void kernel_launch(void* const* d_in, const int* in_sizes, int n_in,
                              void* d_out, int out_size){
    const float* y  = (const float*)d_in[0];
    const float* e  = (const float*)d_in[1];
    const float* W1 = (const float*)d_in[2];
    const float* b1 = (const float*)d_in[3];
    const float* W2 = (const float*)d_in[4];
    const float* b2 = (const float*)d_in[5];

    cudaFuncSetAttribute(rhs_kernel,        cudaFuncAttributeMaxDynamicSharedMemorySize, SMEM_RHS_BYTES);
    cudaFuncSetAttribute(precompute_kernel, cudaFuncAttributeMaxDynamicSharedMemorySize, 147456);

    init_kernel<<<8192,256>>>(y);
    precompute_kernel<<<512,512,147456>>>(e, W1, W2);

    double dt = 1.0/8.0;
    for (int s=0; s<8; s++){
        double t0 = s*dt;
        for (int i=0; i<6; i++){
            float cf[5] = {0.f,0.f,0.f,0.f,0.f};
            for (int j=0; j<i; j++) cf[j] = (float)(dt*ATAB[i][j]);
            rhs_kernel<<<256,512,SMEM_RHS_BYTES>>>(
                (float)(t0 + CTAB[i]*dt), i, cf[0],cf[1],cf[2],cf[3],cf[4],
                W1, b1, W2, b2);
        }
        combine_kernel<<<2048,256>>>((float)dt);
    }
    final_kernel<<<4096,256>>>((float*)d_out, out_size);
}

// round 2
// speedup vs baseline: 1.6040x; 1.6040x over previous
#include <cuda_runtime.h>
#include <math.h>

#define BB 32768
#define DD 64
#define HH 256

// ---------------- device scratch (static, no runtime allocation) ----------------
__device__ float g_y[BB*DD];
__device__ float g_logp[BB];
__device__ float g_kz[6][BB*DD];
__device__ float g_kd[6][BB];
__device__ float g_c[BB*HH];
__device__ float g_csum[BB];

// ---------------- init: copy y, zero logp ----------------
__global__ void init_kernel(const float* __restrict__ y){
    int i = blockIdx.x*256 + threadIdx.x;      // grid covers BB*DD exactly
    g_y[i] = y[i];
    if (i < BB) g_logp[i] = 0.f;
}

// ---------------- precompute: c = (e@W2^T) * (e@W1z), csum = row-sum(c) ----------------
__global__ __launch_bounds__(512,1) void precompute_kernel(
    const float* __restrict__ e, const float* __restrict__ W1, const float* __restrict__ W2){
    extern __shared__ float sm[];
    float* W1s = sm;            // [64][256]
    float* W2T = sm + 16384;    // [64][256]  (transposed W2)
    float* es  = sm + 32768;    // [64][64]
    int tid = threadIdx.x;
    int row0 = blockIdx.x*64;

    for (int i=tid; i<4096; i+=512) ((float4*)W1s)[i] = ((const float4*)W1)[i];
    for (int i=tid; i<HH*DD; i+=512){ int h = i>>6, d = i&63; W2T[d*HH + h] = W2[i]; }
    for (int i=tid; i<1024; i+=512) ((float4*)es)[i] = ((const float4*)(e + (size_t)row0*DD))[i];
    __syncthreads();

    int ry = tid>>5, hx = tid&31;   // rows ry*4..+3, h cols hx*8..+7
    float s1[4][8], s2[4][8];
    #pragma unroll
    for (int i=0;i<4;i++)
        #pragma unroll
        for (int j=0;j<8;j++){ s1[i][j]=0.f; s2[i][j]=0.f; }

    for (int d=0; d<DD; d++){
        float ev[4];
        #pragma unroll
        for (int i=0;i<4;i++) ev[i] = es[(ry*4+i)*DD + d];
        const float* p1 = &W1s[d*HH + hx*8];
        const float* p2 = &W2T[d*HH + hx*8];
        float4 a1 = *(const float4*)p1,  b1v = *(const float4*)(p1+4);
        float4 a2 = *(const float4*)p2,  b2v = *(const float4*)(p2+4);
        float w1v[8] = {a1.x,a1.y,a1.z,a1.w,b1v.x,b1v.y,b1v.z,b1v.w};
        float w2v[8] = {a2.x,a2.y,a2.z,a2.w,b2v.x,b2v.y,b2v.z,b2v.w};
        #pragma unroll
        for (int i=0;i<4;i++)
            #pragma unroll
            for (int j=0;j<8;j++){
                s2[i][j] = fmaf(ev[i], w1v[j], s2[i][j]);
                s1[i][j] = fmaf(ev[i], w2v[j], s1[i][j]);
            }
    }
    #pragma unroll
    for (int i=0;i<4;i++){
        float cv[8]; float p = 0.f;
        #pragma unroll
        for (int j=0;j<8;j++){ cv[j] = s1[i][j]*s2[i][j]; p += cv[j]; }
        int r = row0 + ry*4 + i;
        float4* dst = (float4*)&g_c[(size_t)r*HH + hx*8];
        dst[0] = make_float4(cv[0],cv[1],cv[2],cv[3]);
        dst[1] = make_float4(cv[4],cv[5],cv[6],cv[7]);
        #pragma unroll
        for (int o=16;o;o>>=1) p += __shfl_xor_sync(0xffffffffu, p, o);
        if (hx==0) g_csum[r] = p;
    }
}

// ---------------- fused RHS: yi = y + sum cf_j*k_j ; k_stage = (h@W2+b2, sum c*h^2 - csum) ----------------
#define SMEM_RHS_BYTES (49600*4)

__global__ __launch_bounds__(512,1) void rhs_kernel(
    float t, int stage, float c0,float c1,float c2,float c3,float c4,
    const float* __restrict__ W1, const float* __restrict__ b1,
    const float* __restrict__ W2, const float* __restrict__ b2){
    extern __shared__ float sm[];
    float* W1s = sm;              // [64][256]   16384
    float* W2s = sm + 16384;      // [256][64]   16384
    float* zs  = sm + 32768;      // [128][64]    8192
    float* hs  = sm + 40960;      // [128][65]    8320 (padded vs bank conflicts)
    float* tb  = sm + 49280;      // [256]
    float* b2s = sm + 49536;      // [64]
    int tid = threadIdx.x;
    int row0 = blockIdx.x*128;

    for (int i=tid; i<4096; i+=512) ((float4*)W1s)[i] = ((const float4*)W1)[i];
    for (int i=tid; i<4096; i+=512) ((float4*)W2s)[i] = ((const float4*)W2)[i];
    if (tid < HH)               tb[tid]      = fmaf(t, W1[DD*HH + tid], b1[tid]);
    if (tid >= HH && tid < HH+DD) b2s[tid-HH] = b2[tid-HH];

    const float cf[5] = {c0,c1,c2,c3,c4};
    {
        const float4* ybase = (const float4*)(g_y + (size_t)row0*DD);
        for (int i=tid; i<2048; i+=512){
            float4 v = ybase[i];
            for (int j=0;j<stage;j++){
                float4 k = ((const float4*)(g_kz[j] + (size_t)row0*DD))[i];
                v.x = fmaf(cf[j],k.x,v.x); v.y = fmaf(cf[j],k.y,v.y);
                v.z = fmaf(cf[j],k.z,v.z); v.w = fmaf(cf[j],k.w,v.w);
            }
            ((float4*)zs)[i] = v;
        }
    }
    __syncthreads();

    // ---- GEMM1: a[128x256] = zs[128x64] @ W1s[64x256], 8x8 per-thread tile ----
    int ry = tid>>5, hx = tid&31;      // rows ry*8..+7 ; h cols hx*8..+7
    float acc[8][8];
    #pragma unroll
    for (int i=0;i<8;i++)
        #pragma unroll
        for (int j=0;j<8;j++) acc[i][j] = 0.f;

    for (int d0=0; d0<DD; d0+=4){
        float zq[8][4];
        #pragma unroll
        for (int i=0;i<8;i++){
            float4 z4 = *(const float4*)&zs[(ry*8+i)*DD + d0];
            zq[i][0]=z4.x; zq[i][1]=z4.y; zq[i][2]=z4.z; zq[i][3]=z4.w;
        }
        #pragma unroll
        for (int dd=0; dd<4; dd++){
            const float* wp = &W1s[(d0+dd)*HH + hx*8];
            float4 wa = *(const float4*)wp, wb = *(const float4*)(wp+4);
            float wv[8] = {wa.x,wa.y,wa.z,wa.w,wb.x,wb.y,wb.z,wb.w};
            #pragma unroll
            for (int i=0;i<8;i++){
                float zz = zq[i][dd];
                #pragma unroll
                for (int j=0;j<8;j++) acc[i][j] = fmaf(zz, wv[j], acc[i][j]);
            }
        }
    }

    // ---- bias + tanh + divergence dot (div = csum - sum c*h^2 ; store kd = -div) ----
    float tbv[8];
    #pragma unroll
    for (int j=0;j<8;j++) tbv[j] = tb[hx*8 + j];

    float divp[8];
    #pragma unroll
    for (int i=0;i<8;i++){
        #pragma unroll
        for (int j=0;j<8;j++) acc[i][j] = tanhf(acc[i][j] + tbv[j]);
        const float4* cp = (const float4*)&g_c[(size_t)(row0+ry*8+i)*HH + hx*8];
        float4 ca = cp[0], cb = cp[1];
        float p;
        p  = ca.x*acc[i][0]*acc[i][0];
        p  = fmaf(ca.y*acc[i][1], acc[i][1], p);
        p  = fmaf(ca.z*acc[i][2], acc[i][2], p);
        p  = fmaf(ca.w*acc[i][3], acc[i][3], p);
        p  = fmaf(cb.x*acc[i][4], acc[i][4], p);
        p  = fmaf(cb.y*acc[i][5], acc[i][5], p);
        p  = fmaf(cb.z*acc[i][6], acc[i][6], p);
        p  = fmaf(cb.w*acc[i][7], acc[i][7], p);
        divp[i] = p;
    }
    #pragma unroll
    for (int i=0;i<8;i++){
        float p = divp[i];
        #pragma unroll
        for (int o=16;o;o>>=1) p += __shfl_xor_sync(0xffffffffu, p, o);
        if (hx==0){ int r = row0+ry*8+i; g_kd[stage][r] = p - g_csum[r]; }
    }

    // ---- GEMM2: dz[128x64] = h[128x256] @ W2s[256x64], chunked through smem ----
    int rg = tid>>4, dg = tid&15;      // rows rg*4..+3 ; d cols dg*4..+3
    float dz[4][4];
    #pragma unroll
    for (int i=0;i<4;i++)
        #pragma unroll
        for (int j=0;j<4;j++) dz[i][j] = 0.f;

    for (int ci=0; ci<4; ci++){
        __syncthreads();
        if ((hx>>3) == ci){
            int hb = (hx&7)*8;
            #pragma unroll
            for (int i=0;i<8;i++)
                #pragma unroll
                for (int j=0;j<8;j++)
                    hs[(ry*8+i)*65 + hb + j] = acc[i][j];
        }
        __syncthreads();
        for (int hk=0; hk<64; hk++){
            float hv[4];
            #pragma unroll
            for (int i=0;i<4;i++) hv[i] = hs[(rg*4+i)*65 + hk];
            float4 w = *(const float4*)&W2s[(ci*64+hk)*DD + dg*4];
            #pragma unroll
            for (int i=0;i<4;i++){
                dz[i][0] = fmaf(hv[i], w.x, dz[i][0]);
                dz[i][1] = fmaf(hv[i], w.y, dz[i][1]);
                dz[i][2] = fmaf(hv[i], w.z, dz[i][2]);
                dz[i][3] = fmaf(hv[i], w.w, dz[i][3]);
            }
        }
    }
    float4 bb = *(const float4*)&b2s[dg*4];
    #pragma unroll
    for (int i=0;i<4;i++){
        float4 o = make_float4(dz[i][0]+bb.x, dz[i][1]+bb.y, dz[i][2]+bb.z, dz[i][3]+bb.w);
        *(float4*)&g_kz[stage][(size_t)(row0+rg*4+i)*DD + dg*4] = o;
    }
}

// ---------------- combine: y += dt*sum b_j k_j ; logp += dt*sum b_j kd_j ----------------
__global__ void combine_kernel(float dt){
    int i = blockIdx.x*256 + threadIdx.x;   // over BB*DD/4 float4
    const float b0 = (float)(35.0/384.0);
    const float b2 = (float)(500.0/1113.0);
    const float b3 = (float)(125.0/192.0);
    const float b4 = (float)(-2187.0/6784.0);
    const float b5 = (float)(11.0/84.0);
    float4 y = ((float4*)g_y)[i];
    float4 k0 = ((const float4*)g_kz[0])[i];
    float4 k2 = ((const float4*)g_kz[2])[i];
    float4 k3 = ((const float4*)g_kz[3])[i];
    float4 k4 = ((const float4*)g_kz[4])[i];
    float4 k5 = ((const float4*)g_kz[5])[i];
    float sx = b0*k0.x + b2*k2.x + b3*k3.x + b4*k4.x + b5*k5.x;
    float sy = b0*k0.y + b2*k2.y + b3*k3.y + b4*k4.y + b5*k5.y;
    float sz = b0*k0.z + b2*k2.z + b3*k3.z + b4*k4.z + b5*k5.z;
    float sw = b0*k0.w + b2*k2.w + b3*k3.w + b4*k4.w + b5*k5.w;
    y.x = fmaf(dt, sx, y.x); y.y = fmaf(dt, sy, y.y);
    y.z = fmaf(dt, sz, y.z); y.w = fmaf(dt, sw, y.w);
    ((float4*)g_y)[i] = y;
    if (i < BB){
        float s = b0*g_kd[0][i] + b2*g_kd[2][i] + b3*g_kd[3][i] + b4*g_kd[4][i] + b5*g_kd[5][i];
        g_logp[i] = fmaf(dt, s, g_logp[i]);
    }
}

// ---------------- epilogue: out = [z flat | log_px] ----------------
__global__ void final_kernel(float* __restrict__ out, int out_size){
    int gw = blockIdx.x*256 + threadIdx.x;
    int r = gw >> 5, lane = gw & 31;       // one warp per row
    float z0 = g_y[r*DD + lane];
    float z1 = g_y[r*DD + 32 + lane];
    out[r*DD + lane]      = z0;
    out[r*DD + 32 + lane] = z1;
    float s = fmaf(z0, z0, z1*z1);
    #pragma unroll
    for (int o=16;o;o>>=1) s += __shfl_xor_sync(0xffffffffu, s, o);
    if (lane==0){
        int oidx = BB*DD + r;
        if (oidx < out_size)
            out[oidx] = fmaf(-0.5f, s, -((float)DD)*0.91893853320467274178f) - g_logp[r];
    }
}

// ---------------- host ----------------
static const double A1t[1]={0.2};
static const double A2t[2]={3.0/40.0, 9.0/40.0};
static const double A3t[3]={44.0/45.0, -56.0/15.0, 32.0/9.0};
static const double A4t[4]={19372.0/6561.0, -25360.0/2187.0, 64448.0/6561.0, -212.0/729.0};
static const double A5t[5]={9017.0/3168.0, -355.0/33.0, 46732.0/5247.0, 49.0/176.0, -5103.0/18656.0};
static const double* ATAB[6]={0, A1t, A2t, A3t, A4t, A5t};
static const double CTAB[6]={0.0, 0.2, 0.3, 0.8, 8.0/9.0, 1.0};

extern "C" void kernel_launch(void* const* d_in, const int* in_sizes, int n_in,
                              void* d_out, int out_size){
    const float* y  = (const float*)d_in[0];
    const float* e  = (const float*)d_in[1];
    const float* W1 = (const float*)d_in[2];
    const float* b1 = (const float*)d_in[3];
    const float* W2 = (const float*)d_in[4];
    const float* b2 = (const float*)d_in[5];

    cudaFuncSetAttribute(rhs_kernel,        cudaFuncAttributeMaxDynamicSharedMemorySize, SMEM_RHS_BYTES);
    cudaFuncSetAttribute(precompute_kernel, cudaFuncAttributeMaxDynamicSharedMemorySize, 147456);

    init_kernel<<<8192,256>>>(y);
    precompute_kernel<<<512,512,147456>>>(e, W1, W2);

    double dt = 1.0/8.0;
    for (int s=0; s<8; s++){
        double t0 = s*dt;
        for (int i=0; i<6; i++){
            float cf[5] = {0.f,0.f,0.f,0.f,0.f};
            for (int j=0; j<i; j++) cf[j] = (float)(dt*ATAB[i][j]);
            rhs_kernel<<<256,512,SMEM_RHS_BYTES>>>(
                (float)(t0 + CTAB[i]*dt), i, cf[0],cf[1],cf[2],cf[3],cf[4],
                W1, b1, W2, b2);
        }
        combine_kernel<<<2048,256>>>((float)dt);
    }
    final_kernel<<<4096,256>>>((float*)d_out, out_size);
}

// round 5
// speedup vs baseline: 1.7892x; 1.1155x over previous
#include <cuda_runtime.h>
#include <stdint.h>
#include <math.h>

#define BB 32768
#define DD 64
#define HH 256

// ---------------- device scratch (static, no runtime allocation) ----------------
__device__ float g_y[BB*DD];
__device__ float g_logp[BB];
__device__ float g_kz[6][BB*DD];
__device__ float g_kd[6][BB];
__device__ float g_c[BB*HH];
__device__ float g_csum[BB];

// ---------------- packed f32x2 helpers (FFMA2: only reachable via explicit PTX) ----------------
#define FFMA2(acc, a, b) \
    asm("fma.rn.f32x2 %0, %1, %2, %3;" : "=l"(acc) : "l"(a), "l"(b), "l"(acc))
#define PACK2(dst, lo, hi) \
    asm("mov.b64 %0, {%1, %2};" : "=l"(dst) : "r"(lo), "r"(hi))
#define UNPACK2(lo, hi, src) \
    asm("mov.b64 {%0, %1}, %2;" : "=r"(lo), "=r"(hi) : "l"(src))

// accurate fast tanh: 2 MUFU (ex2, rcp); ~1e-6 rel err
__device__ __forceinline__ float tanh_fast(float x){
    float a = fabsf(x);
    float m = a * -2.8853900817779268f;   // -2*log2(e)
    float e; asm("ex2.approx.f32 %0, %1;" : "=f"(e) : "f"(m));
    float den = 1.f + e;
    float r; asm("rcp.approx.f32 %0, %1;" : "=f"(r) : "f"(den));
    return copysignf((1.f - e) * r, x);
}

// ---------------- init: copy y, zero logp ----------------
__global__ void init_kernel(const float* __restrict__ y){
    int i = blockIdx.x*256 + threadIdx.x;      // grid covers BB*DD exactly
    g_y[i] = y[i];
    if (i < BB) g_logp[i] = 0.f;
}

// ---------------- precompute: c = (e@W2^T) * (e@W1z), csum = row-sum(c) ----------------
__global__ __launch_bounds__(512,1) void precompute_kernel(
    const float* __restrict__ e, const float* __restrict__ W1, const float* __restrict__ W2){
    extern __shared__ float sm[];
    float* W1s = sm;            // [64][256]
    float* W2T = sm + 16384;    // [64][256]  (transposed W2)
    float* es  = sm + 32768;    // [64][64]
    int tid = threadIdx.x;
    int row0 = blockIdx.x*64;

    for (int i=tid; i<4096; i+=512) ((float4*)W1s)[i] = ((const float4*)W1)[i];
    for (int i=tid; i<HH*DD; i+=512){ int h = i>>6, d = i&63; W2T[d*HH + h] = W2[i]; }
    for (int i=tid; i<1024; i+=512) ((float4*)es)[i] = ((const float4*)(e + (size_t)row0*DD))[i];
    __syncthreads();

    int ry = tid>>5, hx = tid&31;   // rows ry*4..+3, h cols hx*8..+7
    float s1[4][8], s2[4][8];
    #pragma unroll
    for (int i=0;i<4;i++)
        #pragma unroll
        for (int j=0;j<8;j++){ s1[i][j]=0.f; s2[i][j]=0.f; }

    for (int d=0; d<DD; d++){
        float ev[4];
        #pragma unroll
        for (int i=0;i<4;i++) ev[i] = es[(ry*4+i)*DD + d];
        const float* p1 = &W1s[d*HH + hx*8];
        const float* p2 = &W2T[d*HH + hx*8];
        float4 a1 = *(const float4*)p1,  b1v = *(const float4*)(p1+4);
        float4 a2 = *(const float4*)p2,  b2v = *(const float4*)(p2+4);
        float w1v[8] = {a1.x,a1.y,a1.z,a1.w,b1v.x,b1v.y,b1v.z,b1v.w};
        float w2v[8] = {a2.x,a2.y,a2.z,a2.w,b2v.x,b2v.y,b2v.z,b2v.w};
        #pragma unroll
        for (int i=0;i<4;i++)
            #pragma unroll
            for (int j=0;j<8;j++){
                s2[i][j] = fmaf(ev[i], w1v[j], s2[i][j]);
                s1[i][j] = fmaf(ev[i], w2v[j], s1[i][j]);
            }
    }
    #pragma unroll
    for (int i=0;i<4;i++){
        float cv[8]; float p = 0.f;
        #pragma unroll
        for (int j=0;j<8;j++){ cv[j] = s1[i][j]*s2[i][j]; p += cv[j]; }
        int r = row0 + ry*4 + i;
        float4* dst = (float4*)&g_c[(size_t)r*HH + hx*8];
        dst[0] = make_float4(cv[0],cv[1],cv[2],cv[3]);
        dst[1] = make_float4(cv[4],cv[5],cv[6],cv[7]);
        #pragma unroll
        for (int o=16;o;o>>=1) p += __shfl_xor_sync(0xffffffffu, p, o);
        if (hx==0) g_csum[r] = p;
    }
}

// ---------------- fused RHS (packed f32x2 math) ----------------
// SMEM float-index map:
//   W1s [64][256]     : 0      .. 16384
//   W2s [256][64]     : 16384  .. 32768
//   zs  [128][64]     : 32768  .. 40960
//   hs  [128][66]     : 40960  .. 49408   (stride 66: even -> 8B-aligned pair stores)
//   tb  [256]         : 49408  .. 49664
//   b2s [64]          : 49664  .. 49728
#define SMEM_RHS_BYTES (49728*4)

__global__ __launch_bounds__(512,1) void rhs_kernel(
    float t, int stage, float c0,float c1,float c2,float c3,float c4,
    const float* __restrict__ W1, const float* __restrict__ b1,
    const float* __restrict__ W2, const float* __restrict__ b2){
    extern __shared__ float sm[];
    float* W1s = sm;
    float* W2s = sm + 16384;
    float* zs  = sm + 32768;
    float* hs  = sm + 40960;
    float* tb  = sm + 49408;
    float* b2s = sm + 49664;
    int tid = threadIdx.x;
    int row0 = blockIdx.x*128;

    for (int i=tid; i<4096; i+=512) ((float4*)W1s)[i] = ((const float4*)W1)[i];
    for (int i=tid; i<4096; i+=512) ((float4*)W2s)[i] = ((const float4*)W2)[i];
    if (tid < HH)                 tb[tid]       = fmaf(t, W1[DD*HH + tid], b1[tid]);
    if (tid >= HH && tid < HH+DD) b2s[tid-HH]   = b2[tid-HH];

    const float cf[5] = {c0,c1,c2,c3,c4};
    {
        const float4* ybase = (const float4*)(g_y + (size_t)row0*DD);
        for (int i=tid; i<2048; i+=512){
            float4 v = ybase[i];
            for (int j=0;j<stage;j++){
                float4 k = ((const float4*)(g_kz[j] + (size_t)row0*DD))[i];
                v.x = fmaf(cf[j],k.x,v.x); v.y = fmaf(cf[j],k.y,v.y);
                v.z = fmaf(cf[j],k.z,v.z); v.w = fmaf(cf[j],k.w,v.w);
            }
            ((float4*)zs)[i] = v;
        }
    }
    __syncthreads();

    // ---- GEMM1 (packed): a[128x256] = zs[128x64] @ W1s[64x256]
    // thread (ry,hx): rows ry*8..+7 ; h col-pairs hx*8 + {0,2,4,6}
    int ry = tid>>5, hx = tid&31;
    unsigned long long acc2[8][4];
    #pragma unroll
    for (int i=0;i<8;i++)
        #pragma unroll
        for (int j=0;j<4;j++) acc2[i][j] = 0ull;

    for (int d0=0; d0<DD; d0+=4){
        float zq[8][4];
        #pragma unroll
        for (int i=0;i<8;i++){
            float4 z4 = *(const float4*)&zs[(ry*8+i)*DD + d0];
            zq[i][0]=z4.x; zq[i][1]=z4.y; zq[i][2]=z4.z; zq[i][3]=z4.w;
        }
        #pragma unroll
        for (int dd=0; dd<4; dd++){
            const ulonglong2* wp = (const ulonglong2*)&W1s[(d0+dd)*HH + hx*8];
            ulonglong2 wa = wp[0], wb = wp[1];
            unsigned long long wv[4] = {wa.x, wa.y, wb.x, wb.y};
            #pragma unroll
            for (int i=0;i<8;i++){
                unsigned long long z2;
                uint32_t zb = __float_as_uint(zq[i][dd]);
                PACK2(z2, zb, zb);
                #pragma unroll
                for (int j=0;j<4;j++) FFMA2(acc2[i][j], z2, wv[j]);
            }
        }
    }

    // ---- bias + tanh + divergence dot; repack tanh'd h into acc2 ----
    size_t grow0 = (size_t)row0;
    #pragma unroll
    for (int i=0;i<8;i++){
        float hv[8];
        #pragma unroll
        for (int j=0;j<4;j++){
            uint32_t u0, u1;
            UNPACK2(u0, u1, acc2[i][j]);
            float f0 = __uint_as_float(u0) + tb[hx*8 + 2*j];
            float f1 = __uint_as_float(u1) + tb[hx*8 + 2*j + 1];
            hv[2*j]   = tanh_fast(f0);
            hv[2*j+1] = tanh_fast(f1);
            PACK2(acc2[i][j], __float_as_uint(hv[2*j]), __float_as_uint(hv[2*j+1]));
        }
        const float4* cp = (const float4*)(g_c + (grow0 + ry*8 + i)*HH + hx*8);
        float4 ca = cp[0], cb = cp[1];
        float p;
        p  = ca.x*hv[0]*hv[0];
        p  = fmaf(ca.y*hv[1], hv[1], p);
        p  = fmaf(ca.z*hv[2], hv[2], p);
        p  = fmaf(ca.w*hv[3], hv[3], p);
        p  = fmaf(cb.x*hv[4], hv[4], p);
        p  = fmaf(cb.y*hv[5], hv[5], p);
        p  = fmaf(cb.z*hv[6], hv[6], p);
        p  = fmaf(cb.w*hv[7], hv[7], p);
        #pragma unroll
        for (int o=16;o;o>>=1) p += __shfl_xor_sync(0xffffffffu, p, o);
        if (hx==0){ int r = row0+ry*8+i; g_kd[stage][r] = p - g_csum[r]; }
    }

    // ---- GEMM2 (packed): dz[128x64] = h[128x256] @ W2s[256x64], chunked via smem ----
    // thread (rg,dg): rows rg*4..+3 ; d col-pairs dg*4 + {0,2}
    int rg = tid>>4, dg = tid&15;
    unsigned long long dz2[4][2];
    {
        const unsigned long long* bp = (const unsigned long long*)&b2s[dg*4];
        unsigned long long bb0 = bp[0], bb1 = bp[1];
        #pragma unroll
        for (int i=0;i<4;i++){ dz2[i][0] = bb0; dz2[i][1] = bb1; }
    }

    for (int ci=0; ci<4; ci++){
        __syncthreads();
        if ((hx>>3) == ci){
            int hb = (hx&7)*8;
            #pragma unroll
            for (int i=0;i<8;i++)
                #pragma unroll
                for (int j=0;j<4;j++)
                    *(unsigned long long*)&hs[(ry*8+i)*66 + hb + 2*j] = acc2[i][j];
        }
        __syncthreads();
        for (int hk=0; hk<64; hk++){
            const ulonglong2* wp = (const ulonglong2*)&W2s[(ci*64+hk)*DD + dg*4];
            ulonglong2 ww = wp[0];
            #pragma unroll
            for (int i=0;i<4;i++){
                uint32_t hb32 = __float_as_uint(hs[(rg*4+i)*66 + hk]);
                unsigned long long h2;
                PACK2(h2, hb32, hb32);
                FFMA2(dz2[i][0], h2, ww.x);
                FFMA2(dz2[i][1], h2, ww.y);
            }
        }
    }
    #pragma unroll
    for (int i=0;i<4;i++){
        uint32_t a0,a1,a2v,a3;
        UNPACK2(a0, a1, dz2[i][0]);
        UNPACK2(a2v, a3, dz2[i][1]);
        float4 o = make_float4(__uint_as_float(a0), __uint_as_float(a1),
                               __uint_as_float(a2v), __uint_as_float(a3));
        *(float4*)&g_kz[stage][(size_t)(row0+rg*4+i)*DD + dg*4] = o;
    }
}

// ---------------- combine: y += dt*sum b_j k_j ; logp += dt*sum b_j kd_j ----------------
__global__ void combine_kernel(float dt){
    int i = blockIdx.x*256 + threadIdx.x;   // over BB*DD/4 float4
    const float b0 = (float)(35.0/384.0);
    const float b2 = (float)(500.0/1113.0);
    const float b3 = (float)(125.0/192.0);
    const float b4 = (float)(-2187.0/6784.0);
    const float b5 = (float)(11.0/84.0);
    float4 y = ((float4*)g_y)[i];
    float4 k0 = ((const float4*)g_kz[0])[i];
    float4 k2 = ((const float4*)g_kz[2])[i];
    float4 k3 = ((const float4*)g_kz[3])[i];
    float4 k4 = ((const float4*)g_kz[4])[i];
    float4 k5 = ((const float4*)g_kz[5])[i];
    float sx = b0*k0.x + b2*k2.x + b3*k3.x + b4*k4.x + b5*k5.x;
    float sy = b0*k0.y + b2*k2.y + b3*k3.y + b4*k4.y + b5*k5.y;
    float sz = b0*k0.z + b2*k2.z + b3*k3.z + b4*k4.z + b5*k5.z;
    float sw = b0*k0.w + b2*k2.w + b3*k3.w + b4*k4.w + b5*k5.w;
    y.x = fmaf(dt, sx, y.x); y.y = fmaf(dt, sy, y.y);
    y.z = fmaf(dt, sz, y.z); y.w = fmaf(dt, sw, y.w);
    ((float4*)g_y)[i] = y;
    if (i < BB){
        float s = b0*g_kd[0][i] + b2*g_kd[2][i] + b3*g_kd[3][i] + b4*g_kd[4][i] + b5*g_kd[5][i];
        g_logp[i] = fmaf(dt, s, g_logp[i]);
    }
}

// ---------------- epilogue: out = [z flat | log_px] ----------------
__global__ void final_kernel(float* __restrict__ out, int out_size){
    int gw = blockIdx.x*256 + threadIdx.x;
    int r = gw >> 5, lane = gw & 31;       // one warp per row
    float z0 = g_y[r*DD + lane];
    float z1 = g_y[r*DD + 32 + lane];
    out[r*DD + lane]      = z0;
    out[r*DD + 32 + lane] = z1;
    float s = fmaf(z0, z0, z1*z1);
    #pragma unroll
    for (int o=16;o;o>>=1) s += __shfl_xor_sync(0xffffffffu, s, o);
    if (lane==0){
        int oidx = BB*DD + r;
        if (oidx < out_size)
            out[oidx] = fmaf(-0.5f, s, -((float)DD)*0.91893853320467274178f) - g_logp[r];
    }
}

// ---------------- host ----------------
static const double A1t[1]={0.2};
static const double A2t[2]={3.0/40.0, 9.0/40.0};
static const double A3t[3]={44.0/45.0, -56.0/15.0, 32.0/9.0};
static const double A4t[4]={19372.0/6561.0, -25360.0/2187.0, 64448.0/6561.0, -212.0/729.0};
static const double A5t[5]={9017.0/3168.0, -355.0/33.0, 46732.0/5247.0, 49.0/176.0, -5103.0/18656.0};
static const double* ATAB[6]={0, A1t, A2t, A3t, A4t, A5t};
static const double CTAB[6]={0.0, 0.2, 0.3, 0.8, 8.0/9.0, 1.0};

extern "C" void kernel_launch(void* const* d_in, const int* in_sizes, int n_in,
                              void* d_out, int out_size){
    const float* y  = (const float*)d_in[0];
    const float* e  = (const float*)d_in[1];
    const float* W1 = (const float*)d_in[2];
    const float* b1 = (const float*)d_in[3];
    const float* W2 = (const float*)d_in[4];
    const float* b2 = (const float*)d_in[5];

    cudaFuncSetAttribute(rhs_kernel,        cudaFuncAttributeMaxDynamicSharedMemorySize, SMEM_RHS_BYTES);
    cudaFuncSetAttribute(precompute_kernel, cudaFuncAttributeMaxDynamicSharedMemorySize, 147456);

    init_kernel<<<8192,256>>>(y);
    precompute_kernel<<<512,512,147456>>>(e, W1, W2);

    double dt = 1.0/8.0;
    for (int s=0; s<8; s++){
        double t0 = s*dt;
        for (int i=0; i<6; i++){
            float cf[5] = {0.f,0.f,0.f,0.f,0.f};
            for (int j=0; j<i; j++) cf[j] = (float)(dt*ATAB[i][j]);
            rhs_kernel<<<256,512,SMEM_RHS_BYTES>>>(
                (float)(t0 + CTAB[i]*dt), i, cf[0],cf[1],cf[2],cf[3],cf[4],
                W1, b1, W2, b2);
        }
        combine_kernel<<<2048,256>>>((float)dt);
    }
    final_kernel<<<4096,256>>>((float*)d_out, out_size);
}